// round 14
// baseline (speedup 1.0000x reference)
#include <cuda_runtime.h>
#include <cstdint>

// ROI Align, NCHW.  input (4,256,200,200) f32, rois (1024,5), out (1024,256,7,7).
// R13 resubmit (prior round hit a broker/container infra failure, as in R3).
// Occupancy push: CTA = (roi, 32ch) as 8 pipelined groups of 4 channels,
// double-buffered: smem 10.4KB; __launch_bounds__(128,14) caps regs at 36
// -> 14 CTAs/SM (was 10, reg+smem capped). Latency-exposure fix.

#define OHW 49
static constexpr int C_   = 256;
static constexpr int H_   = 200;
static constexpr int W_   = 200;
static constexpr int HW_  = H_ * W_;
static constexpr int GC   = 4;              // channels per group
static constexpr int NG   = 8;              // groups per CTA (32 channels)
static constexpr int P_   = 20;             // smem row pitch (floats) = 5 quads
static constexpr int CSTR = 16 * P_ + 4;    // 324 floats per channel plane
static constexpr int BUF  = GC * CSTR;      // 1296 floats per buffer
static constexpr int NT   = 128;

__device__ __forceinline__ void cp_async16(uint32_t s_dst, const void* g_src) {
    asm volatile("cp.async.cg.shared.global [%0], [%1], 16;" :: "r"(s_dst), "l"(g_src));
}
__device__ __forceinline__ void cp_commit() {
    asm volatile("cp.async.commit_group;" ::: "memory");
}
template <int N> __device__ __forceinline__ void cp_wait() {
    asm volatile("cp.async.wait_group %0;" :: "n"(N) : "memory");
}

__global__ __launch_bounds__(NT, 14) void roi_align_kernel(
    const float* __restrict__ inp,
    const float* __restrict__ rois,
    float* __restrict__ out)
{
    __shared__ __align__(16) float tile[2][BUF];       // 10368 B
    __shared__ float s_lx[7], s_ly[7];
    __shared__ int   s_xr[7], s_yo[7];

    const int m   = blockIdx.x;
    const int c0  = blockIdx.y * (GC * NG);
    const int tid = threadIdx.x;

    // ---- per-roi scalars (proven math) ----
    const float* r = rois + (size_t)m * 5;
    const int   b  = (int)r[0];
    const float x1 = r[1] * 0.25f, y1 = r[2] * 0.25f;
    const float bw = fmaxf(r[3] * 0.25f - x1, 1.0f) * (1.0f / 7.0f);
    const float bh = fmaxf(r[4] * 0.25f - y1, 1.0f) * (1.0f / 7.0f);

    const float px0 = ((x1 + 0.5f * bw) * 199.0f) / 200.0f;
    const float px6 = ((x1 + 6.5f * bw) * 199.0f) / 200.0f;
    const float py0 = ((y1 + 0.5f * bh) * 199.0f) / 200.0f;
    const float py6 = ((y1 + 6.5f * bh) * 199.0f) / 200.0f;
    int xlo = max(0, min((int)floorf(px0), W_ - 1));
    int ylo = max(0, min((int)floorf(py0), H_ - 1));
    int xhi = max(xlo, min((int)floorf(px6) + 1, W_ - 1));
    int yhi = max(ylo, min((int)floorf(py6) + 1, H_ - 1));
    const int ww = min(xhi - xlo + 1, 16);
    const int wh = min(yhi - ylo + 1, 16);
    const int ax = min(xlo & ~3, W_ - P_);
    const int nq = min(5, (xlo - ax + ww + 3) >> 2);

    // ---- per-bin params (threads 0..13) ----
    if (tid < 7) {
        const float px = ((x1 + ((float)tid + 0.5f) * bw) * 199.0f) / 200.0f;
        const int   x0 = (int)floorf(px);
        s_lx[tid] = px - (float)x0;
        s_xr[tid] = max(0, min(x0 - ax, P_ - 2));
    } else if (tid < 14) {
        const int   t  = tid - 7;
        const float py = ((y1 + ((float)t + 0.5f) * bh) * 199.0f) / 200.0f;
        const int   y0 = (int)floorf(py);
        s_ly[t] = py - (float)y0;
        s_yo[t] = max(0, min(y0 - ylo, 14)) * P_;
    }

    // ---- staging lane map (once); warp w stages channel w of each group ----
    const int wid  = tid >> 5;               // 0..3
    const int lane = tid & 31;
    const int rrow = lane / 5;               // 0..5 (lanes 30,31 idle)
    const int rq   = lane - rrow * 5;        // 0..4
    const bool act = (lane < 30) && (rq < nq);
    const float* base = inp + ((size_t)b * C_ + c0 + wid) * (size_t)HW_
                            + (size_t)ylo * W_ + ax;
    const bool p0 = act && (rrow      < wh);
    const bool p1 = act && (rrow + 6  < wh);
    const bool p2 = act && (rrow + 12 < wh);
    const uint32_t so0 = (uint32_t)(rrow * P_ + rq * 4) * 4u;
    const uint32_t so1 = so0 + 6u * P_ * 4u;
    const uint32_t so2 = so1 + 6u * P_ * 4u;
    const int go0 = rrow * W_ + rq * 4;

    auto stage = [&](int g, int buf) {
        const float* gp = base + (size_t)(g * GC) * HW_ + go0;
        uint32_t sp = (uint32_t)__cvta_generic_to_shared(tile[buf] + wid * CSTR);
        if (p0) cp_async16(sp + so0, gp);
        if (p1) cp_async16(sp + so1, gp + 6 * W_);
        if (p2) cp_async16(sp + so2, gp + 12 * W_);
        cp_commit();
    };

    stage(0, 0);
    stage(1, 1);

    cp_wait<1>();
    __syncthreads();                         // bin params + group0 visible

    // ---- register-resident bin params ----
    const bool comp = tid < 2 * OHW;         // 98 compute threads
    int cstart = 0, xr = 0, yo = 0;
    float w00 = 0, w01 = 0, w10 = 0, w11 = 0;
    size_t obase = 0;
    if (comp) {
        cstart = (tid >= OHW) ? 1 : 0;
        const int bin = tid - cstart * OHW;
        const int ph  = bin / 7;
        const int pw  = bin - ph * 7;
        const float lx = s_lx[pw], ly = s_ly[ph];
        const float hx = 1.0f - lx, hy = 1.0f - ly;
        w00 = hy * hx; w01 = hy * lx; w10 = ly * hx; w11 = ly * lx;
        xr = s_xr[pw]; yo = s_yo[ph];
        obase = ((size_t)m * C_ + c0 + cstart) * OHW + bin;
    }

    auto compute = [&](int g, int buf) {
        if (comp) {
            const float* tp = tile[buf] + cstart * CSTR + yo + xr;
            float* op = out + obase + (size_t)(g * GC) * OHW;
            #pragma unroll
            for (int k = 0; k < 2; k++, tp += 2 * CSTR, op += 2 * OHW) {
                const float v = w00 * tp[0] + w01 * tp[1]
                              + w10 * tp[P_] + w11 * tp[P_ + 1];
                __stcs(op, v);
            }
        }
    };

    // ---- 8-phase unrolled pipeline, depth 2 ----
    #pragma unroll
    for (int g = 0; g < NG; g++) {
        compute(g, g & 1);
        __syncthreads();                     // buffer consumed
        if (g + 2 < NG) stage(g + 2, g & 1);
        if (g + 1 < NG) {
            if (g + 2 < NG) cp_wait<1>(); else cp_wait<0>();
            __syncthreads();                 // next buffer ready
        }
    }
}

extern "C" void kernel_launch(void* const* d_in, const int* in_sizes, int n_in,
                              void* d_out, int out_size)
{
    const float* inp  = (const float*)d_in[0];
    const float* rois = (const float*)d_in[1];
    float*       out  = (float*)d_out;
    const int M = in_sizes[1] / 5;           // 1024
    dim3 grid(M, C_ / (GC * NG));            // (1024, 8)
    roi_align_kernel<<<grid, NT>>>(inp, rois, out);
}

// round 15
// speedup vs baseline: 1.0921x; 1.0921x over previous
#include <cuda_runtime.h>
#include <cstdint>

// ROI Align, NCHW.  input (4,256,200,200) f32, rois (1024,5), out (1024,256,7,7).
// R15: barrier-free warp-autonomous pipelines. Each warp stages AND computes
// its own 8 channels (4 phases x 2ch, double-buffered cp.async): wait_group
// covers only the warp's own copies -> NO __syncthreads anywhere. Bin params
// register-resident per lane (weights depend only on bin). 40 independent
// warp pipelines/SM instead of 10 lock-stepped CTAs -> smooth DRAM demand.

#define OHW 49
static constexpr int C_   = 256;
static constexpr int H_   = 200;
static constexpr int W_   = 200;
static constexpr int HW_  = H_ * W_;
static constexpr int P_   = 20;             // smem row pitch (floats) = 5 quads
static constexpr int CSTR = 16 * P_ + 4;    // 324 floats per channel plane
static constexpr int NT   = 128;

__device__ __forceinline__ void cp_async16(uint32_t s_dst, const void* g_src) {
    asm volatile("cp.async.cg.shared.global [%0], [%1], 16;" :: "r"(s_dst), "l"(g_src));
}
__device__ __forceinline__ void cp_commit() {
    asm volatile("cp.async.commit_group;" ::: "memory");
}
template <int N> __device__ __forceinline__ void cp_wait() {
    asm volatile("cp.async.wait_group %0;" :: "n"(N) : "memory");
}

__global__ __launch_bounds__(NT, 10) void roi_align_kernel(
    const float* __restrict__ inp,
    const float* __restrict__ rois,
    float* __restrict__ out)
{
    // tile[buf][warp][ch][plane] : 2*4*2*324*4 = 20736 B
    __shared__ __align__(16) float tile[2][4][2][CSTR];

    const int m    = blockIdx.x;
    const int c0   = blockIdx.y * 32;
    const int tid  = threadIdx.x;
    const int wid  = tid >> 5;
    const int lane = tid & 31;

    // ---- per-roi scalars (proven math; uniform across warp) ----
    const float* r = rois + (size_t)m * 5;
    const int   b  = (int)r[0];
    const float x1 = r[1] * 0.25f, y1 = r[2] * 0.25f;
    const float bw = fmaxf(r[3] * 0.25f - x1, 1.0f) * (1.0f / 7.0f);
    const float bh = fmaxf(r[4] * 0.25f - y1, 1.0f) * (1.0f / 7.0f);

    const float px0f = ((x1 + 0.5f * bw) * 199.0f) / 200.0f;
    const float px6f = ((x1 + 6.5f * bw) * 199.0f) / 200.0f;
    const float py0f = ((y1 + 0.5f * bh) * 199.0f) / 200.0f;
    const float py6f = ((y1 + 6.5f * bh) * 199.0f) / 200.0f;
    int xlo = max(0, min((int)floorf(px0f), W_ - 1));
    int ylo = max(0, min((int)floorf(py0f), H_ - 1));
    int xhi = max(xlo, min((int)floorf(px6f) + 1, W_ - 1));
    int yhi = max(ylo, min((int)floorf(py6f) + 1, H_ - 1));
    const int ww = min(xhi - xlo + 1, 16);
    const int wh = min(yhi - ylo + 1, 16);
    const int ax = min(xlo & ~3, W_ - P_);
    const int nq = min(5, (xlo - ax + ww + 3) >> 2);

    // ---- staging lane map: lane -> (sc, row0, q); 6 predicated quads ----
    const int sc   = lane / 15;              // 0,1 (lanes 30,31 -> 2, masked off)
    const int slot = lane - sc * 15;
    const int row0 = slot / 5;               // 0..2
    const int q    = slot - row0 * 5;        // 0..4
    const bool lact = (lane < 30) && (q < nq);

    bool     pk[6];
    uint32_t sok[6];
    int      gok[6];
    #pragma unroll
    for (int k = 0; k < 6; k++) {
        const int y = row0 + 3 * k;
        pk[k]  = lact && (y < wh);
        sok[k] = (uint32_t)(y * P_ + q * 4) * 4u;
        gok[k] = y * W_ + q * 4;
    }
    const float* cb = inp + ((size_t)(b * C_ + c0 + 8 * wid + sc)) * HW_
                          + (size_t)ylo * W_ + ax;
    const uint32_t sp0 = (uint32_t)__cvta_generic_to_shared(&tile[0][wid][sc][0]);
    const uint32_t sp1 = (uint32_t)__cvta_generic_to_shared(&tile[1][wid][sc][0]);

    auto stage = [&](int g, int buf) {
        const float* gp = cb + (size_t)(2 * g) * HW_;
        const uint32_t sp = buf ? sp1 : sp0;
        #pragma unroll
        for (int k = 0; k < 6; k++)
            if (pk[k]) cp_async16(sp + sok[k], gp + gok[k]);
        cp_commit();
    };

    // ---- register-resident bin params: binA = lane, binB = lane+32 ----
    const int  binA = lane;
    const int  binB = lane + 32;
    const bool vB   = lane < 17;

    auto binparams = [&](int bin, float& w00, float& w01, float& w10, float& w11,
                         int& xryo) {
        const int ph = bin / 7;
        const int pw = bin - ph * 7;
        const float px = ((x1 + ((float)pw + 0.5f) * bw) * 199.0f) / 200.0f;
        const float py = ((y1 + ((float)ph + 0.5f) * bh) * 199.0f) / 200.0f;
        const int x0 = (int)floorf(px);
        const int y0 = (int)floorf(py);
        const float lx = px - (float)x0;
        const float ly = py - (float)y0;
        const float hx = 1.0f - lx, hy = 1.0f - ly;
        w00 = hy * hx; w01 = hy * lx; w10 = ly * hx; w11 = ly * lx;
        xryo = min(max(y0 - ylo, 0), 14) * P_ + min(max(x0 - ax, 0), P_ - 2);
    };

    float wA00, wA01, wA10, wA11, wB00, wB01, wB10, wB11;
    int xryoA, xryoB;
    binparams(binA, wA00, wA01, wA10, wA11, xryoA);
    binparams(binB, wB00, wB01, wB10, wB11, xryoB);   // harmless if !vB (masked)

    float* const outm = out + (size_t)m * (C_ * OHW);
    const uint32_t boffA = (uint32_t)((c0 + 8 * wid) * OHW + binA);

    auto compute = [&](int g, int buf) {
        const float* tb = &tile[buf][wid][0][0];
        #pragma unroll
        for (int c = 0; c < 2; c++) {
            const float* tA = tb + c * CSTR + xryoA;
            const float vA = wA00 * tA[0] + wA01 * tA[1]
                           + wA10 * tA[P_] + wA11 * tA[P_ + 1];
            __stcs(outm + boffA + (2 * g + c) * OHW, vA);
            if (vB) {
                const float* tB = tb + c * CSTR + xryoB;
                const float uB = wB00 * tB[0] + wB01 * tB[1]
                               + wB10 * tB[P_] + wB11 * tB[P_ + 1];
                __stcs(outm + boffA + 32 + (2 * g + c) * OHW, uB);
            }
        }
    };

    // ---- per-warp pipeline, depth 2, no CTA barriers ----
    stage(0, 0);
    stage(1, 1);
    cp_wait<1>(); __syncwarp();
    compute(0, 0); __syncwarp();
    stage(2, 0);
    cp_wait<1>(); __syncwarp();
    compute(1, 1); __syncwarp();
    stage(3, 1);
    cp_wait<1>(); __syncwarp();
    compute(2, 0);
    cp_wait<0>(); __syncwarp();
    compute(3, 1);
}

extern "C" void kernel_launch(void* const* d_in, const int* in_sizes, int n_in,
                              void* d_out, int out_size)
{
    const float* inp  = (const float*)d_in[0];
    const float* rois = (const float*)d_in[1];
    float*       out  = (float*)d_out;
    const int M = in_sizes[1] / 5;           // 1024
    dim3 grid(M, C_ / 32);                   // (1024, 8)
    roi_align_kernel<<<grid, NT>>>(inp, rois, out);
}